// round 6
// baseline (speedup 1.0000x reference)
#include <cuda_runtime.h>
#include <cuda_bf16.h>
#include <cstdint>

// CrossAttentionModel_20684562497797
//
// Reference math collapses: softmax over a size-1 axis == 1.0 exactly for any
// finite input; mean over heads of ones == 1.0. Output is ones((2048,2048))
// independent of all inputs -> the only mandatory work is writing 16 MiB of 1.0f.
//
// R5 analysis: float4-STG version was LSU-issue bound (1M STG.128 @ ~1/cyc/SM
// ~= 4us), not bandwidth bound (L2 only 25.9%). This version routes the fill
// through TMA bulk copies: each CTA fills a 32 KiB smem tile with 1.0f once,
// then a single thread issues cp.async.bulk shared->global for its chunk.
// Store bytes now hit the LTS write port (~6300 B/cyc chip-wide) with ~1
// issued instruction per 32 KiB instead of 2048 STG.128s.

static __device__ __forceinline__ uint32_t smem_u32(const void* p) {
    uint32_t a;
    asm("{ .reg .u64 t; cvta.to.shared.u64 t, %1; cvt.u32.u64 %0, t; }"
        : "=r"(a) : "l"(p));
    return a;
}

static constexpr int CHUNK_BYTES = 32768;           // 32 KiB per CTA chunk
static constexpr int CHUNK_FLOATS = CHUNK_BYTES / 4; // 8192

__global__ __launch_bounds__(128)
void fill_ones_tma_kernel(float* __restrict__ out, long long total_bytes) {
    __shared__ __align__(128) float buf[CHUNK_FLOATS];

    // Fill the 32 KiB smem tile with 1.0f: 128 threads x 16 STS.128.
    const float4 one4 = make_float4(1.0f, 1.0f, 1.0f, 1.0f);
    float4* b4 = reinterpret_cast<float4*>(buf);
    #pragma unroll
    for (int i = 0; i < CHUNK_FLOATS / 4 / 128; i++) {
        b4[threadIdx.x + i * 128] = one4;
    }
    __syncthreads();

    // Order generic-proxy smem writes before the async-proxy bulk copy.
    asm volatile("fence.proxy.async.shared::cta;" ::: "memory");

    if (threadIdx.x == 0) {
        long long off = (long long)blockIdx.x * CHUNK_BYTES;
        if (off < total_bytes) {
            long long rem = total_bytes - off;
            unsigned bytes = (unsigned)(rem < CHUNK_BYTES ? rem : CHUNK_BYTES);
            // bytes is a multiple of 16 for this problem (16 MiB total);
            // mask down defensively (bulk copy requires 16B granularity).
            bytes &= ~15u;
            if (bytes) {
                uint32_t saddr = smem_u32(buf);
                char* gaddr = reinterpret_cast<char*>(out) + off;
                asm volatile(
                    "cp.async.bulk.global.shared::cta.bulk_group [%0], [%1], %2;"
                    :: "l"(gaddr), "r"(saddr), "r"(bytes) : "memory");
                asm volatile("cp.async.bulk.commit_group;" ::: "memory");
                asm volatile("cp.async.bulk.wait_group 0;" ::: "memory");
            }
        }
    }
}

extern "C" void kernel_launch(void* const* d_in, const int* in_sizes, int n_in,
                              void* d_out, int out_size) {
    (void)d_in; (void)in_sizes; (void)n_in;

    float* out = (float*)d_out;
    long long total_bytes = (long long)out_size * 4;  // 16 MiB for 2048x2048

    int blocks = (int)((total_bytes + CHUNK_BYTES - 1) / CHUNK_BYTES);  // 512
    fill_ones_tma_kernel<<<blocks, 128>>>(out, total_bytes);
}